// round 4
// baseline (speedup 1.0000x reference)
#include <cuda_runtime.h>
#include <math.h>

#define NSc 16
#define NVc 8
#define HEc 32
#define Dc  40
#define NNODES 10000
#define NEDGES 160000
#define C110f 0.57735026918962576f
#define C111f 0.70710678118654752f
#define EPSf 1e-5f
#define EB 8   // edges per warp-group

typedef unsigned long long ull;

// ---------------- device scratch ----------------
__device__ float g_q[NNODES * Dc];
__device__ float g_attn[NEDGES];
__device__ float g_expv[NEDGES];
__device__ float g_vout[NEDGES * Dc];
__device__ float g_m[NNODES];
__device__ float g_denom[NNODES];
__device__ float g_upd[NNODES * Dc];
__device__ float g_bn[40];

// ---------------- helpers ----------------
__device__ __forceinline__ void atomicMaxF(float* addr, float v) {
    if (v >= 0.0f) atomicMax((int*)addr, __float_as_int(v));
    else           atomicMin((unsigned int*)addr, __float_as_uint(v));
}
__device__ __forceinline__ ull pack2(float x) {
    ull r;
    asm("mov.b64 %0, {%1, %1};" : "=l"(r) : "f"(x));
    return r;
}
__device__ __forceinline__ void unpack2(ull v, float& a, float& b) {
    asm("mov.b64 {%0, %1}, %2;" : "=f"(a), "=f"(b) : "l"(v));
}
__device__ __forceinline__ void fma2(ull& d, ull a, ull b) {
    asm("fma.rn.f32x2 %0, %1, %2, %0;" : "+l"(d) : "l"(a), "l"(b));
}

// ---------------- init ----------------
__global__ void k_init() {
    int t = blockIdx.x * blockDim.x + threadIdx.x;
    if (t < NNODES) {
        g_m[t] = __int_as_float(0xff800000);
        g_denom[t] = 0.f;
    }
    if (t < NNODES * Dc) g_upd[t] = 0.f;
    if (t < 40) g_bn[t] = 0.f;
}

// ---------------- per-node query projection ----------------
__global__ void k_q(const float* __restrict__ atom,
                    const float* __restrict__ Wqs,
                    const float* __restrict__ Wqv) {
    __shared__ float sWs[NSc * NSc];
    __shared__ float sWv[NVc * NVc];
    int tid = threadIdx.x;
    for (int i = tid; i < NSc * NSc; i += blockDim.x) sWs[i] = Wqs[i];
    for (int i = tid; i < NVc * NVc; i += blockDim.x) sWv[i] = Wqv[i];
    __syncthreads();
    int n = blockIdx.x * blockDim.x + tid;
    if (n >= NNODES) return;
    float s[NSc], v[NVc * 3];
    #pragma unroll
    for (int i = 0; i < NSc; i++) s[i] = atom[n * Dc + i];
    #pragma unroll
    for (int i = 0; i < NVc * 3; i++) v[i] = atom[n * Dc + NSc + i];
    #pragma unroll
    for (int o = 0; o < NSc; o++) {
        float acc = 0.f;
        #pragma unroll
        for (int i = 0; i < NSc; i++) acc = fmaf(s[i], sWs[i * NSc + o], acc);
        g_q[n * Dc + o] = acc;
    }
    #pragma unroll
    for (int o = 0; o < NVc; o++) {
        #pragma unroll
        for (int d = 0; d < 3; d++) {
            float acc = 0.f;
            #pragma unroll
            for (int i = 0; i < NVc; i++) acc = fmaf(v[i * 3 + d], sWv[i * NVc + o], acc);
            g_q[n * Dc + NSc + o * 3 + d] = acc;
        }
    }
}

// ---------------- fused edge kernel ----------------
struct __align__(16) WS {
    float sq[Dc][EB];        // gathered q (transposed)
    float xs_[NSc][EB];      // x_s
    float as_[NSc][EB];      // x_s * sh_s
    float dotc_[NVc][EB];    // C110 * (x_v . sh_v)
    float xvs_[NVc * 3][EB]; // x_v * sh_s
    float crossc_[NVc * 3][EB]; // C111 * (x_v x sh_v)
    float shv_[3][EB];
    float shs_[EB];
    int ssrc[EB];
};
static_assert(sizeof(WS) == 4256, "WS size");

#define SMEM_WEIGHT_FLOATS (2*32*640 + 2*640 + 2*32*32 + 2*32)
#define SMEM_EDGE_BYTES (SMEM_WEIGHT_FLOATS * 4 + 8 * (int)sizeof(WS))

// Output mapping: for warp-lane `lane`, pair index p in [0,10), the b64
// accumulator acc[p][e] holds flat outputs n0 = 64p + 2*lane (low half, q=0)
// and n0+1 (high half, q=1) for edge e. Region decode:
//   p 0..3  -> w1 (16x16): i = 4p + (lane>>3),      o = 2*(lane&7)+q
//   p 4..5  -> w2 ( 8x16): i = 4(p-4) + (lane>>3),  o = 2*(lane&7)+q
//   p 6..7  -> w3 (16x 8): i = 8(p-6) + (lane>>2),  o = 2*(lane&3)+q
//   p 8     -> w4 ( 8x 8): i = lane>>2,             o = 2*(lane&3)+q
//   p 9     -> w5 ( 8x 8): i = lane>>2,             o = 2*(lane&3)+q
__device__ __forceinline__ void process_mat(
    int mat, const float (&hreg)[EB], WS* ws,
    const float* sW2, const float* sB2, int lane, int e0)
{
    ull acc[10][EB];
    {
        const ull* bp = (const ull*)(sB2 + mat * 640) + lane;
        #pragma unroll
        for (int p = 0; p < 10; p++) {
            ull b = bp[p * 32];
            #pragma unroll
            for (int e = 0; e < EB; e++) acc[p][e] = b;
        }
    }
    const ull* wbase = (const ull*)(sW2 + mat * 20480) + lane;
    #pragma unroll 2
    for (int j = 0; j < 32; j++) {
        const ull* wr = wbase + j * 320;
        ull hb[EB];
        #pragma unroll
        for (int e = 0; e < EB; e++)
            hb[e] = pack2(__shfl_sync(0xffffffffu, hreg[e], j));
        #pragma unroll
        for (int p = 0; p < 10; p++) {
            ull w = wr[p * 32];
            #pragma unroll
            for (int e = 0; e < EB; e++) fma2(acc[p][e], w, hb[e]);
        }
    }

    int ih8 = lane >> 3;
    int ih4 = lane >> 2;

    // ---- scalar outputs ----
    float ps0[EB], ps1[EB];
    #pragma unroll
    for (int e = 0; e < EB; e++) {
        float s0 = 0.f, s1 = 0.f, x0, x1;
        #pragma unroll
        for (int p = 0; p < 4; p++) {
            float c = ws->as_[4 * p + ih8][e];
            unpack2(acc[p][e], x0, x1);
            s0 = fmaf(c, x0, s0); s1 = fmaf(c, x1, s1);
        }
        #pragma unroll
        for (int p = 4; p < 6; p++) {
            float c = ws->dotc_[4 * (p - 4) + ih8][e];
            unpack2(acc[p][e], x0, x1);
            s0 = fmaf(c, x0, s0); s1 = fmaf(c, x1, s1);
        }
        s0 += __shfl_xor_sync(0xffffffffu, s0, 8);
        s0 += __shfl_xor_sync(0xffffffffu, s0, 16);
        s1 += __shfl_xor_sync(0xffffffffu, s1, 8);
        s1 += __shfl_xor_sync(0xffffffffu, s1, 16);
        ps0[e] = s0; ps1[e] = s1;
    }

    // ---- vector pieces ----
    float p30[EB], p31[EB], a80[EB], a81[EB], a90[EB], a91[EB];
    #pragma unroll
    for (int e = 0; e < EB; e++) {
        float s0 = 0.f, s1 = 0.f, x0, x1;
        #pragma unroll
        for (int p = 6; p < 8; p++) {
            float c = ws->xs_[8 * (p - 6) + ih4][e];
            unpack2(acc[p][e], x0, x1);
            s0 = fmaf(c, x0, s0); s1 = fmaf(c, x1, s1);
        }
        p30[e] = s0; p31[e] = s1;
        unpack2(acc[8][e], a80[e], a81[e]);
        unpack2(acc[9][e], a90[e], a91[e]);
    }

    float t[EB];
    if (mat == 0) {
        #pragma unroll
        for (int e = 0; e < EB; e++) {
            float v = 0.f;
            if (lane < 8)
                v = fmaf(ps0[e], ws->sq[2 * lane][e],
                         ps1[e] * ws->sq[2 * lane + 1][e]);
            t[e] = v;
        }
    } else {
        if (lane < 8) {
            #pragma unroll
            for (int e = 0; e < EB; e++) {
                g_vout[(e0 + e) * Dc + 2 * lane]     = ps0[e];
                g_vout[(e0 + e) * Dc + 2 * lane + 1] = ps1[e];
            }
        }
    }

    #pragma unroll 1
    for (int d = 0; d < 3; d++) {
        float pv0[EB], pv1[EB];
        #pragma unroll
        for (int e = 0; e < EB; e++) {
            float sh = ws->shv_[d][e];
            float c4 = ws->xvs_[3 * ih4 + d][e];
            float c5 = ws->crossc_[3 * ih4 + d][e];
            float v0 = fmaf(p30[e], sh, fmaf(a80[e], c4, a90[e] * c5));
            float v1 = fmaf(p31[e], sh, fmaf(a81[e], c4, a91[e] * c5));
            v0 += __shfl_xor_sync(0xffffffffu, v0, 4);
            v0 += __shfl_xor_sync(0xffffffffu, v0, 8);
            v0 += __shfl_xor_sync(0xffffffffu, v0, 16);
            v1 += __shfl_xor_sync(0xffffffffu, v1, 4);
            v1 += __shfl_xor_sync(0xffffffffu, v1, 8);
            v1 += __shfl_xor_sync(0xffffffffu, v1, 16);
            pv0[e] = v0; pv1[e] = v1;
        }
        if (mat == 0) {
            if (lane < 4) {
                #pragma unroll
                for (int e = 0; e < EB; e++) {
                    t[e] = fmaf(pv0[e], ws->sq[16 + 6 * lane + d][e],
                           fmaf(pv1[e], ws->sq[16 + 6 * lane + 3 + d][e], t[e]));
                }
            }
        } else {
            if (lane < 4) {
                #pragma unroll
                for (int e = 0; e < EB; e++) {
                    g_vout[(e0 + e) * Dc + 16 + 6 * lane + d]     = pv0[e];
                    g_vout[(e0 + e) * Dc + 16 + 6 * lane + 3 + d] = pv1[e];
                }
            }
        }
    }

    if (mat == 0) {
        #pragma unroll
        for (int e = 0; e < EB; e++) {
            float v = t[e];
            #pragma unroll
            for (int off = 16; off > 0; off >>= 1)
                v += __shfl_xor_sync(0xffffffffu, v, off);
            t[e] = v;
        }
        if (lane == 0) {
            #pragma unroll
            for (int e = 0; e < EB; e++) {
                g_attn[e0 + e] = t[e];
                atomicMaxF(&g_m[ws->ssrc[e]], t[e]);
            }
        }
    }
}

__global__ void __launch_bounds__(256, 1) k_edge(
    const float* __restrict__ atom, const float* __restrict__ efeat,
    const float* __restrict__ esh,
    const float* __restrict__ kw1, const float* __restrict__ kb1,
    const float* __restrict__ kw2, const float* __restrict__ kb2,
    const float* __restrict__ vw1, const float* __restrict__ vb1,
    const float* __restrict__ vw2, const float* __restrict__ vb2,
    const int* __restrict__ eidx)
{
    extern __shared__ float smem[];
    float* sW2 = smem;                 // [2][32][640]
    float* sB2 = sW2 + 2 * 32 * 640;   // [2][640]
    float* sW1 = sB2 + 2 * 640;        // [2][32][32]
    float* sB1 = sW1 + 2 * 32 * 32;    // [2][32]
    WS* wsbase = (WS*)(sB1 + 64);

    int tid = threadIdx.x;
    for (int i = tid; i < 32 * 640; i += 256) { sW2[i] = kw2[i]; sW2[20480 + i] = vw2[i]; }
    for (int i = tid; i < 640; i += 256)      { sB2[i] = kb2[i]; sB2[640 + i] = vb2[i]; }
    for (int i = tid; i < 1024; i += 256)     { sW1[i] = kw1[i]; sW1[1024 + i] = vw1[i]; }
    if (tid < 32) { sB1[tid] = kb1[tid]; sB1[32 + tid] = vb1[tid]; }
    __syncthreads();

    int wid = tid >> 5, lane = tid & 31;
    WS* ws = wsbase + wid;
    int gwarp = blockIdx.x * 8 + wid;
    int nwarps = gridDim.x * 8;

    for (int g = gwarp; g < NEDGES / EB; g += nwarps) {
        int e0 = g * EB;
        int dstA[EB];
        float efr[EB];
        #pragma unroll
        for (int e = 0; e < EB; e++) {
            int edge = e0 + e;
            int dst = eidx[edge];
            int src = eidx[NEDGES + edge];
            dstA[e] = dst;
            ws->sq[lane][e] = g_q[src * Dc + lane];
            if (lane < 8) ws->sq[32 + lane][e] = g_q[src * Dc + 32 + lane];
            efr[e] = efeat[edge * HEc + lane];
            if (lane == 0) ws->ssrc[e] = src;
            if (lane < 4) {
                float sv = esh[edge * 4 + lane];
                if (lane == 0) ws->shs_[e] = sv;
                else ws->shv_[lane - 1][e] = sv;
            }
        }
        __syncwarp();
        #pragma unroll
        for (int e = 0; e < EB; e++) {
            float s0 = ws->shs_[e];
            if (lane < 16) {
                float x = atom[dstA[e] * Dc + lane];
                ws->xs_[lane][e] = x;
                ws->as_[lane][e] = x * s0;
            } else if (lane < 24) {
                int i = lane - 16;
                float ax = atom[dstA[e] * Dc + 16 + 3 * i];
                float ay = atom[dstA[e] * Dc + 17 + 3 * i];
                float az = atom[dstA[e] * Dc + 18 + 3 * i];
                float bx = ws->shv_[0][e], by = ws->shv_[1][e], bz = ws->shv_[2][e];
                ws->dotc_[i][e] = C110f * (ax * bx + ay * by + az * bz);
                ws->crossc_[3 * i + 0][e] = C111f * (ay * bz - az * by);
                ws->crossc_[3 * i + 1][e] = C111f * (az * bx - ax * bz);
                ws->crossc_[3 * i + 2][e] = C111f * (ax * by - ay * bx);
                ws->xvs_[3 * i + 0][e] = ax * s0;
                ws->xvs_[3 * i + 1][e] = ay * s0;
                ws->xvs_[3 * i + 2][e] = az * s0;
            }
        }
        __syncwarp();
        // hidden layer, both MLPs (lane = hidden unit, edge features via shfl)
        float hk[EB], hv[EB];
        {
            float bk = sB1[lane], bv = sB1[32 + lane];
            #pragma unroll
            for (int e = 0; e < EB; e++) { hk[e] = bk; hv[e] = bv; }
            #pragma unroll 4
            for (int j = 0; j < 32; j++) {
                float wk = sW1[j * 32 + lane];
                float wv = sW1[1024 + j * 32 + lane];
                #pragma unroll
                for (int e = 0; e < EB; e++) {
                    float ef = __shfl_sync(0xffffffffu, efr[e], j);
                    hk[e] = fmaf(wk, ef, hk[e]);
                    hv[e] = fmaf(wv, ef, hv[e]);
                }
            }
            #pragma unroll
            for (int e = 0; e < EB; e++) {
                hk[e] = fmaxf(hk[e], 0.f);
                hv[e] = fmaxf(hv[e], 0.f);
            }
        }
        process_mat(0, hk, ws, sW2, sB2, lane, e0);
        process_mat(1, hv, ws, sW2, sB2, lane, e0);
        __syncwarp();
    }
}

// ---------------- softmax exp + denom ----------------
__global__ void k_exp(const int* __restrict__ eidx) {
    int e = blockIdx.x * blockDim.x + threadIdx.x;
    if (e >= NEDGES) return;
    int src = eidx[NEDGES + e];
    float m = g_m[src];
    if (!isfinite(m)) m = 0.f;
    float ev = expf(g_attn[e] - m);
    g_expv[e] = ev;
    atomicAdd(&g_denom[src], ev);
}

// ---------------- scatter v*a ----------------
__global__ void k_scatter(const int* __restrict__ eidx) {
    int idx = blockIdx.x * blockDim.x + threadIdx.x;
    if (idx >= NEDGES * Dc) return;
    int e = idx / Dc;
    int c = idx - e * Dc;
    int src = eidx[NEDGES + e];
    float a = g_expv[e] / g_denom[src];
    atomicAdd(&g_upd[src * Dc + c], g_vout[idx] * a);
}

// ---------------- batchnorm stats ----------------
__global__ void k_bnstats(const float* __restrict__ atom) {
    __shared__ float r1[256], r2[256];
    int b = blockIdx.x;
    int tid = threadIdx.x;
    float s1 = 0.f, s2 = 0.f;
    if (b < 16) {
        for (int n = tid; n < NNODES; n += 256) {
            float y = atom[n * Dc + b] + g_upd[n * Dc + b];
            s1 += y;
            s2 += y * y;
        }
    } else {
        int i = b - 16;
        for (int n = tid; n < NNODES; n += 256) {
            int base = n * Dc + 16 + 3 * i;
            float y0 = atom[base + 0] + g_upd[base + 0];
            float y1 = atom[base + 1] + g_upd[base + 1];
            float y2 = atom[base + 2] + g_upd[base + 2];
            s1 += y0 * y0 + y1 * y1 + y2 * y2;
        }
    }
    r1[tid] = s1; r2[tid] = s2;
    __syncthreads();
    for (int off = 128; off > 0; off >>= 1) {
        if (tid < off) { r1[tid] += r1[tid + off]; r2[tid] += r2[tid + off]; }
        __syncthreads();
    }
    if (tid == 0) {
        if (b < 16) { g_bn[b] = r1[0]; g_bn[16 + b] = r2[0]; }
        else        { g_bn[16 + b] = r1[0]; }
    }
}

// ---------------- final output ----------------
__global__ void k_out(const float* __restrict__ atom,
                      const float* __restrict__ bws, const float* __restrict__ bbs,
                      const float* __restrict__ bwv, float* __restrict__ out) {
    int idx = blockIdx.x * blockDim.x + threadIdx.x;
    if (idx >= NNODES * Dc) return;
    int n = idx / Dc;
    int c = idx - n * Dc;
    float y = atom[idx] + g_upd[idx];
    float r;
    if (c < 16) {
        float mu = g_bn[c] * (1.f / NNODES);
        float var = g_bn[16 + c] * (1.f / NNODES) - mu * mu;
        r = (y - mu) * rsqrtf(var + EPSf) * bws[c] + bbs[c];
    } else {
        int i = (c - 16) / 3;
        float norm = g_bn[32 + i] * (1.f / (3.f * NNODES));
        r = y * rsqrtf(norm + EPSf) * bwv[i];
    }
    out[idx] = r;
}

// ---------------- launch ----------------
extern "C" void kernel_launch(void* const* d_in, const int* in_sizes, int n_in,
                              void* d_out, int out_size) {
    const float* atom = (const float*)d_in[0];
    const float* efeat = (const float*)d_in[1];
    const float* esh  = (const float*)d_in[2];
    const float* Wqs  = (const float*)d_in[3];
    const float* Wqv  = (const float*)d_in[4];
    const float* kw1  = (const float*)d_in[5];
    const float* kb1  = (const float*)d_in[6];
    const float* kw2  = (const float*)d_in[7];
    const float* kb2  = (const float*)d_in[8];
    const float* vw1  = (const float*)d_in[9];
    const float* vb1  = (const float*)d_in[10];
    const float* vw2  = (const float*)d_in[11];
    const float* vb2  = (const float*)d_in[12];
    const float* bws  = (const float*)d_in[13];
    const float* bbs  = (const float*)d_in[14];
    const float* bwv  = (const float*)d_in[15];
    const int*   eidx = (const int*)d_in[16];
    float* out = (float*)d_out;

    cudaFuncSetAttribute(k_edge, cudaFuncAttributeMaxDynamicSharedMemorySize,
                         SMEM_EDGE_BYTES);

    k_init<<<(NNODES * Dc + 255) / 256, 256>>>();
    k_q<<<(NNODES + 255) / 256, 256>>>(atom, Wqs, Wqv);
    k_edge<<<148, 256, SMEM_EDGE_BYTES>>>(atom, efeat, esh,
                                          kw1, kb1, kw2, kb2,
                                          vw1, vb1, vw2, vb2, eidx);
    k_exp<<<(NEDGES + 255) / 256, 256>>>(eidx);
    k_scatter<<<(NEDGES * Dc + 255) / 256, 256>>>(eidx);
    k_bnstats<<<24, 256>>>(atom);
    k_out<<<(NNODES * Dc + 255) / 256, 256>>>(atom, bws, bbs, bwv, out);

    long long need = (long long)NNODES * Dc + (long long)NEDGES * HEc;
    if (out_size >= need) {
        cudaMemcpyAsync(out + NNODES * Dc, efeat,
                        (size_t)NEDGES * HEc * sizeof(float),
                        cudaMemcpyDeviceToDevice);
    }
}

// round 5
// speedup vs baseline: 1.0394x; 1.0394x over previous
#include <cuda_runtime.h>
#include <math.h>

#define NSc 16
#define NVc 8
#define HEc 32
#define Dc  40
#define NNODES 10000
#define NEDGES 160000
#define C110f 0.57735026918962576f
#define C111f 0.70710678118654752f
#define EPSf 1e-5f
#define EB 4   // edges per warp-group (4 => acc fits in regs, no spills)

typedef unsigned long long ull;

// ---------------- device scratch ----------------
__device__ float g_q[NNODES * Dc];
__device__ float g_attn[NEDGES];
__device__ float g_expv[NEDGES];
__device__ float g_vout[NEDGES * Dc];
__device__ float g_m[NNODES];
__device__ float g_denom[NNODES];
__device__ float g_upd[NNODES * Dc];
__device__ float g_bn[40];

// ---------------- helpers ----------------
__device__ __forceinline__ void atomicMaxF(float* addr, float v) {
    if (v >= 0.0f) atomicMax((int*)addr, __float_as_int(v));
    else           atomicMin((unsigned int*)addr, __float_as_uint(v));
}
__device__ __forceinline__ ull pack2(float x) {
    ull r;
    asm("mov.b64 %0, {%1, %1};" : "=l"(r) : "f"(x));
    return r;
}
__device__ __forceinline__ void unpack2(ull v, float& a, float& b) {
    asm("mov.b64 {%0, %1}, %2;" : "=f"(a), "=f"(b) : "l"(v));
}
__device__ __forceinline__ void fma2(ull& d, ull a, ull b) {
    asm("fma.rn.f32x2 %0, %1, %2, %0;" : "+l"(d) : "l"(a), "l"(b));
}

// ---------------- init ----------------
__global__ void k_init() {
    int t = blockIdx.x * blockDim.x + threadIdx.x;
    if (t < NNODES) {
        g_m[t] = __int_as_float(0xff800000);
        g_denom[t] = 0.f;
    }
    if (t < NNODES * Dc) g_upd[t] = 0.f;
    if (t < 40) g_bn[t] = 0.f;
}

// ---------------- per-node query projection ----------------
__global__ void k_q(const float* __restrict__ atom,
                    const float* __restrict__ Wqs,
                    const float* __restrict__ Wqv) {
    __shared__ float sWs[NSc * NSc];
    __shared__ float sWv[NVc * NVc];
    int tid = threadIdx.x;
    for (int i = tid; i < NSc * NSc; i += blockDim.x) sWs[i] = Wqs[i];
    for (int i = tid; i < NVc * NVc; i += blockDim.x) sWv[i] = Wqv[i];
    __syncthreads();
    int n = blockIdx.x * blockDim.x + tid;
    if (n >= NNODES) return;
    float s[NSc], v[NVc * 3];
    #pragma unroll
    for (int i = 0; i < NSc; i++) s[i] = atom[n * Dc + i];
    #pragma unroll
    for (int i = 0; i < NVc * 3; i++) v[i] = atom[n * Dc + NSc + i];
    #pragma unroll
    for (int o = 0; o < NSc; o++) {
        float acc = 0.f;
        #pragma unroll
        for (int i = 0; i < NSc; i++) acc = fmaf(s[i], sWs[i * NSc + o], acc);
        g_q[n * Dc + o] = acc;
    }
    #pragma unroll
    for (int o = 0; o < NVc; o++) {
        #pragma unroll
        for (int d = 0; d < 3; d++) {
            float acc = 0.f;
            #pragma unroll
            for (int i = 0; i < NVc; i++) acc = fmaf(v[i * 3 + d], sWv[i * NVc + o], acc);
            g_q[n * Dc + NSc + o * 3 + d] = acc;
        }
    }
}

// ---------------- fused edge kernel ----------------
struct __align__(16) WS {
    float sq[Dc][EB];        // gathered q (transposed)
    float xs_[NSc][EB];      // x_s
    float as_[NSc][EB];      // x_s * sh_s
    float dotc_[NVc][EB];    // C110 * (x_v . sh_v)
    float xvs_[NVc * 3][EB]; // x_v * sh_s
    float crossc_[NVc * 3][EB]; // C111 * (x_v x sh_v)
    float shv_[3][EB];
    float shs_[EB];
    int ssrc[EB];
};
static_assert(sizeof(WS) == 2128, "WS size");

#define SMEM_WEIGHT_FLOATS (2*32*640 + 2*640 + 2*32*32 + 2*32)
#define SMEM_EDGE_BYTES (SMEM_WEIGHT_FLOATS * 4 + 8 * (int)sizeof(WS))

// Output mapping: for warp-lane `lane`, pair index p in [0,10), the b64
// accumulator acc[p][e] holds flat outputs n0 = 64p + 2*lane (low half, q=0)
// and n0+1 (high half, q=1) for edge e. Region decode:
//   p 0..3  -> w1 (16x16): i = 4p + (lane>>3),      o = 2*(lane&7)+q
//   p 4..5  -> w2 ( 8x16): i = 4(p-4) + (lane>>3),  o = 2*(lane&7)+q
//   p 6..7  -> w3 (16x 8): i = 8(p-6) + (lane>>2),  o = 2*(lane&3)+q
//   p 8     -> w4 ( 8x 8): i = lane>>2,             o = 2*(lane&3)+q
//   p 9     -> w5 ( 8x 8): i = lane>>2,             o = 2*(lane&3)+q
__device__ __forceinline__ void process_mat(
    int mat, const float (&hreg)[EB], WS* ws,
    const float* sW2, const float* sB2, int lane, int e0)
{
    ull acc[10][EB];
    {
        const ull* bp = (const ull*)(sB2 + mat * 640) + lane;
        #pragma unroll
        for (int p = 0; p < 10; p++) {
            ull b = bp[p * 32];
            #pragma unroll
            for (int e = 0; e < EB; e++) acc[p][e] = b;
        }
    }
    const ull* wbase = (const ull*)(sW2 + mat * 20480) + lane;
    #pragma unroll 4
    for (int j = 0; j < 32; j++) {
        const ull* wr = wbase + j * 320;
        ull hb[EB];
        #pragma unroll
        for (int e = 0; e < EB; e++)
            hb[e] = pack2(__shfl_sync(0xffffffffu, hreg[e], j));
        #pragma unroll
        for (int p = 0; p < 10; p++) {
            ull w = wr[p * 32];
            #pragma unroll
            for (int e = 0; e < EB; e++) fma2(acc[p][e], w, hb[e]);
        }
    }

    int ih8 = lane >> 3;
    int ih4 = lane >> 2;

    // ---- scalar outputs ----
    float ps0[EB], ps1[EB];
    #pragma unroll
    for (int e = 0; e < EB; e++) {
        float s0 = 0.f, s1 = 0.f, x0, x1;
        #pragma unroll
        for (int p = 0; p < 4; p++) {
            float c = ws->as_[4 * p + ih8][e];
            unpack2(acc[p][e], x0, x1);
            s0 = fmaf(c, x0, s0); s1 = fmaf(c, x1, s1);
        }
        #pragma unroll
        for (int p = 4; p < 6; p++) {
            float c = ws->dotc_[4 * (p - 4) + ih8][e];
            unpack2(acc[p][e], x0, x1);
            s0 = fmaf(c, x0, s0); s1 = fmaf(c, x1, s1);
        }
        s0 += __shfl_xor_sync(0xffffffffu, s0, 8);
        s0 += __shfl_xor_sync(0xffffffffu, s0, 16);
        s1 += __shfl_xor_sync(0xffffffffu, s1, 8);
        s1 += __shfl_xor_sync(0xffffffffu, s1, 16);
        ps0[e] = s0; ps1[e] = s1;
    }

    // ---- vector pieces ----
    float p30[EB], p31[EB], a80[EB], a81[EB], a90[EB], a91[EB];
    #pragma unroll
    for (int e = 0; e < EB; e++) {
        float s0 = 0.f, s1 = 0.f, x0, x1;
        #pragma unroll
        for (int p = 6; p < 8; p++) {
            float c = ws->xs_[8 * (p - 6) + ih4][e];
            unpack2(acc[p][e], x0, x1);
            s0 = fmaf(c, x0, s0); s1 = fmaf(c, x1, s1);
        }
        p30[e] = s0; p31[e] = s1;
        unpack2(acc[8][e], a80[e], a81[e]);
        unpack2(acc[9][e], a90[e], a91[e]);
    }

    float t[EB];
    if (mat == 0) {
        #pragma unroll
        for (int e = 0; e < EB; e++) {
            float v = 0.f;
            if (lane < 8)
                v = fmaf(ps0[e], ws->sq[2 * lane][e],
                         ps1[e] * ws->sq[2 * lane + 1][e]);
            t[e] = v;
        }
    } else {
        if (lane < 8) {
            #pragma unroll
            for (int e = 0; e < EB; e++) {
                g_vout[(e0 + e) * Dc + 2 * lane]     = ps0[e];
                g_vout[(e0 + e) * Dc + 2 * lane + 1] = ps1[e];
            }
        }
    }

    #pragma unroll 1
    for (int d = 0; d < 3; d++) {
        float pv0[EB], pv1[EB];
        #pragma unroll
        for (int e = 0; e < EB; e++) {
            float sh = ws->shv_[d][e];
            float c4 = ws->xvs_[3 * ih4 + d][e];
            float c5 = ws->crossc_[3 * ih4 + d][e];
            float v0 = fmaf(p30[e], sh, fmaf(a80[e], c4, a90[e] * c5));
            float v1 = fmaf(p31[e], sh, fmaf(a81[e], c4, a91[e] * c5));
            v0 += __shfl_xor_sync(0xffffffffu, v0, 4);
            v0 += __shfl_xor_sync(0xffffffffu, v0, 8);
            v0 += __shfl_xor_sync(0xffffffffu, v0, 16);
            v1 += __shfl_xor_sync(0xffffffffu, v1, 4);
            v1 += __shfl_xor_sync(0xffffffffu, v1, 8);
            v1 += __shfl_xor_sync(0xffffffffu, v1, 16);
            pv0[e] = v0; pv1[e] = v1;
        }
        if (mat == 0) {
            if (lane < 4) {
                #pragma unroll
                for (int e = 0; e < EB; e++) {
                    t[e] = fmaf(pv0[e], ws->sq[16 + 6 * lane + d][e],
                           fmaf(pv1[e], ws->sq[16 + 6 * lane + 3 + d][e], t[e]));
                }
            }
        } else {
            if (lane < 4) {
                #pragma unroll
                for (int e = 0; e < EB; e++) {
                    g_vout[(e0 + e) * Dc + 16 + 6 * lane + d]     = pv0[e];
                    g_vout[(e0 + e) * Dc + 16 + 6 * lane + 3 + d] = pv1[e];
                }
            }
        }
    }

    if (mat == 0) {
        #pragma unroll
        for (int e = 0; e < EB; e++) {
            float v = t[e];
            #pragma unroll
            for (int off = 16; off > 0; off >>= 1)
                v += __shfl_xor_sync(0xffffffffu, v, off);
            t[e] = v;
        }
        if (lane == 0) {
            #pragma unroll
            for (int e = 0; e < EB; e++) {
                g_attn[e0 + e] = t[e];
                atomicMaxF(&g_m[ws->ssrc[e]], t[e]);
            }
        }
    }
}

__global__ void __launch_bounds__(256, 1) k_edge(
    const float* __restrict__ atom, const float* __restrict__ efeat,
    const float* __restrict__ esh,
    const float* __restrict__ kw1, const float* __restrict__ kb1,
    const float* __restrict__ kw2, const float* __restrict__ kb2,
    const float* __restrict__ vw1, const float* __restrict__ vb1,
    const float* __restrict__ vw2, const float* __restrict__ vb2,
    const int* __restrict__ eidx)
{
    extern __shared__ float smem[];
    float* sW2 = smem;                 // [2][32][640]
    float* sB2 = sW2 + 2 * 32 * 640;   // [2][640]
    float* sW1 = sB2 + 2 * 640;        // [2][32][32]
    float* sB1 = sW1 + 2 * 32 * 32;    // [2][32]
    WS* wsbase = (WS*)(sB1 + 64);

    int tid = threadIdx.x;
    for (int i = tid; i < 32 * 640; i += 256) { sW2[i] = kw2[i]; sW2[20480 + i] = vw2[i]; }
    for (int i = tid; i < 640; i += 256)      { sB2[i] = kb2[i]; sB2[640 + i] = vb2[i]; }
    for (int i = tid; i < 1024; i += 256)     { sW1[i] = kw1[i]; sW1[1024 + i] = vw1[i]; }
    if (tid < 32) { sB1[tid] = kb1[tid]; sB1[32 + tid] = vb1[tid]; }
    __syncthreads();

    int wid = tid >> 5, lane = tid & 31;
    WS* ws = wsbase + wid;
    int gwarp = blockIdx.x * 8 + wid;
    int nwarps = gridDim.x * 8;

    for (int g = gwarp; g < NEDGES / EB; g += nwarps) {
        int e0 = g * EB;
        int dstA[EB];
        float efr[EB];
        #pragma unroll
        for (int e = 0; e < EB; e++) {
            int edge = e0 + e;
            int dst = eidx[edge];
            int src = eidx[NEDGES + edge];
            dstA[e] = dst;
            ws->sq[lane][e] = g_q[src * Dc + lane];
            if (lane < 8) ws->sq[32 + lane][e] = g_q[src * Dc + 32 + lane];
            efr[e] = efeat[edge * HEc + lane];
            if (lane == 0) ws->ssrc[e] = src;
            if (lane < 4) {
                float sv = esh[edge * 4 + lane];
                if (lane == 0) ws->shs_[e] = sv;
                else ws->shv_[lane - 1][e] = sv;
            }
        }
        __syncwarp();
        #pragma unroll
        for (int e = 0; e < EB; e++) {
            float s0 = ws->shs_[e];
            if (lane < 16) {
                float x = atom[dstA[e] * Dc + lane];
                ws->xs_[lane][e] = x;
                ws->as_[lane][e] = x * s0;
            } else if (lane < 24) {
                int i = lane - 16;
                float ax = atom[dstA[e] * Dc + 16 + 3 * i];
                float ay = atom[dstA[e] * Dc + 17 + 3 * i];
                float az = atom[dstA[e] * Dc + 18 + 3 * i];
                float bx = ws->shv_[0][e], by = ws->shv_[1][e], bz = ws->shv_[2][e];
                ws->dotc_[i][e] = C110f * (ax * bx + ay * by + az * bz);
                ws->crossc_[3 * i + 0][e] = C111f * (ay * bz - az * by);
                ws->crossc_[3 * i + 1][e] = C111f * (az * bx - ax * bz);
                ws->crossc_[3 * i + 2][e] = C111f * (ax * by - ay * bx);
                ws->xvs_[3 * i + 0][e] = ax * s0;
                ws->xvs_[3 * i + 1][e] = ay * s0;
                ws->xvs_[3 * i + 2][e] = az * s0;
            }
        }
        __syncwarp();
        // hidden layer, both MLPs (lane = hidden unit, edge features via shfl)
        float hk[EB], hv[EB];
        {
            float bk = sB1[lane], bv = sB1[32 + lane];
            #pragma unroll
            for (int e = 0; e < EB; e++) { hk[e] = bk; hv[e] = bv; }
            #pragma unroll 4
            for (int j = 0; j < 32; j++) {
                float wk = sW1[j * 32 + lane];
                float wv = sW1[1024 + j * 32 + lane];
                #pragma unroll
                for (int e = 0; e < EB; e++) {
                    float ef = __shfl_sync(0xffffffffu, efr[e], j);
                    hk[e] = fmaf(wk, ef, hk[e]);
                    hv[e] = fmaf(wv, ef, hv[e]);
                }
            }
            #pragma unroll
            for (int e = 0; e < EB; e++) {
                hk[e] = fmaxf(hk[e], 0.f);
                hv[e] = fmaxf(hv[e], 0.f);
            }
        }
        process_mat(0, hk, ws, sW2, sB2, lane, e0);
        process_mat(1, hv, ws, sW2, sB2, lane, e0);
        __syncwarp();
    }
}

// ---------------- softmax exp + denom ----------------
__global__ void k_exp(const int* __restrict__ eidx) {
    int e = blockIdx.x * blockDim.x + threadIdx.x;
    if (e >= NEDGES) return;
    int src = eidx[NEDGES + e];
    float m = g_m[src];
    if (!isfinite(m)) m = 0.f;
    float ev = expf(g_attn[e] - m);
    g_expv[e] = ev;
    atomicAdd(&g_denom[src], ev);
}

// ---------------- scatter v*a ----------------
__global__ void k_scatter(const int* __restrict__ eidx) {
    int idx = blockIdx.x * blockDim.x + threadIdx.x;
    if (idx >= NEDGES * Dc) return;
    int e = idx / Dc;
    int c = idx - e * Dc;
    int src = eidx[NEDGES + e];
    float a = g_expv[e] / g_denom[src];
    atomicAdd(&g_upd[src * Dc + c], g_vout[idx] * a);
}

// ---------------- batchnorm stats ----------------
__global__ void k_bnstats(const float* __restrict__ atom) {
    __shared__ float r1[256], r2[256];
    int b = blockIdx.x;
    int tid = threadIdx.x;
    float s1 = 0.f, s2 = 0.f;
    if (b < 16) {
        for (int n = tid; n < NNODES; n += 256) {
            float y = atom[n * Dc + b] + g_upd[n * Dc + b];
            s1 += y;
            s2 += y * y;
        }
    } else {
        int i = b - 16;
        for (int n = tid; n < NNODES; n += 256) {
            int base = n * Dc + 16 + 3 * i;
            float y0 = atom[base + 0] + g_upd[base + 0];
            float y1 = atom[base + 1] + g_upd[base + 1];
            float y2 = atom[base + 2] + g_upd[base + 2];
            s1 += y0 * y0 + y1 * y1 + y2 * y2;
        }
    }
    r1[tid] = s1; r2[tid] = s2;
    __syncthreads();
    for (int off = 128; off > 0; off >>= 1) {
        if (tid < off) { r1[tid] += r1[tid + off]; r2[tid] += r2[tid + off]; }
        __syncthreads();
    }
    if (tid == 0) {
        if (b < 16) { g_bn[b] = r1[0]; g_bn[16 + b] = r2[0]; }
        else        { g_bn[16 + b] = r1[0]; }
    }
}

// ---------------- final output ----------------
__global__ void k_out(const float* __restrict__ atom,
                      const float* __restrict__ bws, const float* __restrict__ bbs,
                      const float* __restrict__ bwv, float* __restrict__ out) {
    int idx = blockIdx.x * blockDim.x + threadIdx.x;
    if (idx >= NNODES * Dc) return;
    int n = idx / Dc;
    int c = idx - n * Dc;
    float y = atom[idx] + g_upd[idx];
    float r;
    if (c < 16) {
        float mu = g_bn[c] * (1.f / NNODES);
        float var = g_bn[16 + c] * (1.f / NNODES) - mu * mu;
        r = (y - mu) * rsqrtf(var + EPSf) * bws[c] + bbs[c];
    } else {
        int i = (c - 16) / 3;
        float norm = g_bn[32 + i] * (1.f / (3.f * NNODES));
        r = y * rsqrtf(norm + EPSf) * bwv[i];
    }
    out[idx] = r;
}

// ---------------- launch ----------------
extern "C" void kernel_launch(void* const* d_in, const int* in_sizes, int n_in,
                              void* d_out, int out_size) {
    const float* atom = (const float*)d_in[0];
    const float* efeat = (const float*)d_in[1];
    const float* esh  = (const float*)d_in[2];
    const float* Wqs  = (const float*)d_in[3];
    const float* Wqv  = (const float*)d_in[4];
    const float* kw1  = (const float*)d_in[5];
    const float* kb1  = (const float*)d_in[6];
    const float* kw2  = (const float*)d_in[7];
    const float* kb2  = (const float*)d_in[8];
    const float* vw1  = (const float*)d_in[9];
    const float* vb1  = (const float*)d_in[10];
    const float* vw2  = (const float*)d_in[11];
    const float* vb2  = (const float*)d_in[12];
    const float* bws  = (const float*)d_in[13];
    const float* bbs  = (const float*)d_in[14];
    const float* bwv  = (const float*)d_in[15];
    const int*   eidx = (const int*)d_in[16];
    float* out = (float*)d_out;

    cudaFuncSetAttribute(k_edge, cudaFuncAttributeMaxDynamicSharedMemorySize,
                         SMEM_EDGE_BYTES);

    k_init<<<(NNODES * Dc + 255) / 256, 256>>>();
    k_q<<<(NNODES + 255) / 256, 256>>>(atom, Wqs, Wqv);
    k_edge<<<148, 256, SMEM_EDGE_BYTES>>>(atom, efeat, esh,
                                          kw1, kb1, kw2, kb2,
                                          vw1, vb1, vw2, vb2, eidx);
    k_exp<<<(NEDGES + 255) / 256, 256>>>(eidx);
    k_scatter<<<(NEDGES * Dc + 255) / 256, 256>>>(eidx);
    k_bnstats<<<24, 256>>>(atom);
    k_out<<<(NNODES * Dc + 255) / 256, 256>>>(atom, bws, bbs, bwv, out);

    long long need = (long long)NNODES * Dc + (long long)NEDGES * HEc;
    if (out_size >= need) {
        cudaMemcpyAsync(out + NNODES * Dc, efeat,
                        (size_t)NEDGES * HEc * sizeof(float),
                        cudaMemcpyDeviceToDevice);
    }
}